// round 13
// baseline (speedup 1.0000x reference)
#include <cuda_runtime.h>

#define BB 64
#define HH 14
#define WWD 14
#define HW 196
#define CC 32
#define OO 10
#define NCH 14              // em hw-chunks per batch
#define HWB (HW/NCH)        // 14
#define TPB 320
#define MCH 28              // pass0 hw-chunks per batch
#define MHW (HW/MCH)        // 7
#define EPSF 1e-9f
#define LOG2PI 1.8378770664093453f

typedef unsigned long long u64;

// ---- f32x2 packed math (Blackwell) ---------------------------------------
__device__ __forceinline__ u64 pack2(float lo, float hi) {
    u64 r; asm("mov.b64 %0, {%1,%2};" : "=l"(r) : "f"(lo), "f"(hi)); return r;
}
__device__ __forceinline__ u64 pdup(float x) { return pack2(x, x); }
__device__ __forceinline__ void unpack2(u64 v, float& lo, float& hi) {
    asm("mov.b64 {%0,%1}, %2;" : "=f"(lo), "=f"(hi) : "l"(v));
}
__device__ __forceinline__ u64 fma2(u64 a, u64 b, u64 c) {
    u64 d; asm("fma.rn.f32x2 %0,%1,%2,%3;" : "=l"(d) : "l"(a), "l"(b), "l"(c)); return d;
}
__device__ __forceinline__ u64 mul2(u64 a, u64 b) {
    u64 d; asm("mul.rn.f32x2 %0,%1,%2;" : "=l"(d) : "l"(a), "l"(b)); return d;
}
__device__ __forceinline__ u64 add2(u64 a, u64 b) {
    u64 d; asm("add.rn.f32x2 %0,%1,%2;" : "=l"(d) : "l"(a), "l"(b)); return d;
}

// Scratch (fully rewritten every pass -> deterministic, graph-safe)
__device__ float g_partials[BB*NCH*OO*33]; // [b][chunk][o][S0,S1[16],S2[16]]
__device__ float g_params[BB*OO*33];       // [b][o][K, ivar[16], muinv[16]]
__device__ float g_mom[BB*MCH*CC*70];      // pass0 partial moments
__device__ int   g_count[BB];              // em counters (winner resets)
__device__ int   g_cnt0[BB];               // pass0 counters (winner resets)

// ===========================================================================
// PASS 0 via moments (rr = 1/O). Warp-split moment accumulation:
// block=256 (8 warps), lane = c, warp = moment subset, 7 hw per block.
// Moment layout per c (69): [0]=sum a; [1..16]=sum a*p_j;
// [17+10i+idx(j<=k)] = sum a*p_{4i+j}*p_{4i+k};
// [57]=sum a*ow [58]=a*oh [59]=a*ow^2 [60]=a*oh^2
// [61..64]=a*ow*p_{0..3}  [65..68]=a*oh*p_{4..7}.
// Winner block per b: sum 28 chunks, assemble S1/S2 per (o,d), write params.
// ===========================================================================
__global__ void __launch_bounds__(256)
caps_mom(const float* __restrict__ pose,
         const float* __restrict__ act,
         const float* __restrict__ w,
         const float* __restrict__ beta_a,
         const float* __restrict__ beta_u)
{
    __shared__ float sp[MHW][CC][21];   // stride 21: conflict-free scalar reads
    __shared__ float sa[MHW][CC];
    __shared__ int   s_win;

    const int ch  = blockIdx.x;
    const int b   = blockIdx.y;
    const int hw0 = ch * MHW;
    const int tid = threadIdx.x;
    const int wm  = tid >> 5;
    const int c   = tid & 31;

    // ---- tile load --------------------------------------------------------
    {
        const float4* src4 = (const float4*)(pose + (size_t)(b * HW + hw0) * CC * 16);
        for (int idx = tid; idx < MHW * CC * 4; idx += 256) {
            const int cell = idx >> 2;          // t*32+c
            const int q    = idx & 3;
            const float4 f = src4[idx];
            float* dst = &sp[0][0][0] + cell * 21 + q * 4;
            dst[0] = f.x; dst[1] = f.y; dst[2] = f.z; dst[3] = f.w;
        }
        const float* asrc = act + (size_t)(b * HW + hw0) * CC;
        for (int idx = tid; idx < MHW * CC; idx += 256)
            sa[idx >> 5][idx & 31] = asrc[idx];
    }
    __syncthreads();

    float A[10];
    #pragma unroll
    for (int m = 0; m < 10; m++) A[m] = 0.f;

    for (int t = 0; t < MHW; t++) {
        const int hw   = hw0 + t;
        const int h    = hw / WWD;
        const int wpos = hw - h * WWD;
        const float ow = (wpos + 0.5f) * (1.0f / WWD);
        const float oh = (h    + 0.5f) * (1.0f / HH);
        const float a  = sa[t][c];
        const float* P = sp[t][c];

        if (wm == 0) {                 // m0..8 : a, a*p0..7
            A[0] += a;
            #pragma unroll
            for (int j = 0; j < 8; j++) A[1 + j] += a * P[j];
        } else if (wm == 1) {          // m9..16 : a*p8..15
            #pragma unroll
            for (int j = 0; j < 8; j++) A[j] += a * P[8 + j];
        } else if (wm >= 2 && wm <= 5) { // M block i = wm-2
            const int pb = (wm - 2) * 4;
            float p0 = P[pb], p1 = P[pb+1], p2 = P[pb+2], p3 = P[pb+3];
            float q0 = a*p0, q1 = a*p1, q2 = a*p2, q3 = a*p3;
            A[0] += q0*p0; A[1] += q0*p1; A[2] += q0*p2; A[3] += q0*p3;
            A[4] += q1*p1; A[5] += q1*p2; A[6] += q1*p3;
            A[7] += q2*p2; A[8] += q2*p3;
            A[9] += q3*p3;
        } else if (wm == 6) {          // m57..62
            const float aw = a * ow, ah = a * oh;
            A[0] += aw; A[1] += ah;
            A[2] += aw * ow; A[3] += ah * oh;
            A[4] += aw * P[0]; A[5] += aw * P[1];
        } else {                       // wm==7 : m63..68
            const float aw = a * ow, ah = a * oh;
            A[0] += aw * P[2]; A[1] += aw * P[3];
            A[2] += ah * P[4]; A[3] += ah * P[5];
            A[4] += ah * P[6]; A[5] += ah * P[7];
        }
    }

    // ---- write per-(c) partials (no cross-lane reduce needed) ------------
    {
        const int base_tbl[8] = {0, 9, 17, 27, 37, 47, 57, 63};
        const int cnt_tbl[8]  = {9, 8, 10, 10, 10, 10, 6, 6};
        const int mb = base_tbl[wm], mc_ = cnt_tbl[wm];
        float* dst = g_mom + (size_t)((b * MCH + ch) * CC + c) * 70 + mb;
        for (int k = 0; k < mc_; k++) dst[k] = A[k];
    }

    // ---- winner block per batch combines ----------------------------------
    __syncthreads();
    if (tid == 0) {
        __threadfence();
        int prev = atomicAdd(&g_cnt0[b], 1);
        s_win = (prev == MCH - 1);
    }
    __syncthreads();
    if (!s_win) return;
    __threadfence();

    float (*mom)[70] = (float (*)[70])(&sp[0][0][0]);   // alias dead tile
    for (int idx = tid; idx < CC * 69; idx += 256) {
        const int cc = idx / 69;
        const int m  = idx - cc * 69;
        float s = 0.f;
        #pragma unroll 4
        for (int g = 0; g < MCH; g++)
            s += g_mom[(size_t)((b * MCH + g) * CC + cc) * 70 + m];
        mom[cc][m] = s;
    }
    __syncthreads();

    if (tid < OO * 16) {
        const int o   = tid >> 4;
        const int d   = tid & 15;
        const int i   = d >> 2;
        const int col = d & 3;

        float R0 = 0.f, S1 = 0.f, S2 = 0.f;
        for (int cc = 0; cc < CC; cc++) {
            const float* mc2 = mom[cc];
            const float* wc = w + ((size_t)(cc * OO + o) * 16) + col;
            const float w0 = wc[0], w1 = wc[4], w2 = wc[8], w3 = wc[12];
            R0 += mc2[0];
            const float* m1 = mc2 + 1 + i * 4;
            S1 += m1[0]*w0 + m1[1]*w1 + m1[2]*w2 + m1[3]*w3;
            const float* M = mc2 + 17 + i * 10;
            S2 += w0*w0*M[0] + w1*w1*M[4] + w2*w2*M[7] + w3*w3*M[9]
                + 2.f*(w0*w1*M[1] + w0*w2*M[2] + w0*w3*M[3]
                     + w1*w2*M[5] + w1*w3*M[6] + w2*w3*M[8]);
            if (d == 3) {
                S1 += mc2[57];
                S2 += mc2[59] + 2.f*(mc2[61]*w0 + mc2[62]*w1 + mc2[63]*w2 + mc2[64]*w3);
            }
            if (d == 7) {
                S1 += mc2[58];
                S2 += mc2[60] + 2.f*(mc2[65]*w0 + mc2[66]*w1 + mc2[67]*w2 + mc2[68]*w3);
            }
        }
        const float rs     = 0.1f * R0 + EPSF;
        const float inv_rs = 1.0f / rs;
        const float mu     = 0.1f * S1 * inv_rs;
        const float var    = fmaxf(0.1f * S2 * inv_rs - mu * mu, 0.0f) + EPSF;
        const float lv     = __logf(var);
        const float ivar   = 1.0f / var;
        const float muinv  = mu * ivar;
        const float mive   = mu * muinv;

        float sumlv = lv, summive = mive;
        #pragma unroll
        for (int off = 1; off < 16; off <<= 1) {
            sumlv   += __shfl_xor_sync(0xFFFFFFFFu, sumlv,   off);
            summive += __shfl_xor_sync(0xFFFFFFFFu, summive, off);
        }

        const float cost = rs * (16.0f * beta_u[o] + 0.5f * sumlv);
        const float actv = 1.0f / (1.0f + __expf(-(beta_a[o] - cost))); // inv_temp=1

        float* pp = g_params + (size_t)(b * OO + o) * 33;
        pp[1 + d]  = ivar;
        pp[17 + d] = muinv;
        if (d == 0)
            pp[0] = __logf(actv + EPSF)
                  - 0.5f * (16.0f * LOG2PI + sumlv)
                  - 0.5f * summive;
    }
    if (tid == 0) g_cnt0[b] = 0;
}

// ===========================================================================
// EM passes 1/2: batched 3-barrier softmax.
//  P1 : all 14 t -> logits s -> ss[t][c][o]          (1 barrier after)
//  P2a: all 14 t -> e = exp(s - max_o)  -> se        (1 barrier after)
//  P2b: all 14 t -> den = sum_o e; recompute votes; accumulate
// Dynamic smem: sp4(35840) prm(1280) sa(1792) ss(19712) se(19712) Ksm swin.
// ===========================================================================
#define SMEM_EM (35840 + 1280 + 1792 + 19712 + 19712 + 64)

template<int FINAL>
__global__ void __launch_bounds__(TPB, 2)
caps_em(const float* __restrict__ pose,
        const float* __restrict__ act,
        const float* __restrict__ w,
        const float* __restrict__ beta_a,
        const float* __restrict__ beta_u,
        float inv_temp,
        float* __restrict__ out)
{
    extern __shared__ char smraw[];
    float4* sp4 = (float4*)smraw;                       // [14][32][5]
    float4* prm = (float4*)(smraw + 35840);             // [OO*8]
    float*  sa  = (float*)(smraw + 35840 + 1280);       // [448]
    float*  ss  = (float*)(smraw + 35840 + 1280 + 1792);        // [448*11]
    float*  se  = ss + 448 * 11;
    float*  Ksm = se + 448 * 11;                        // [OO]
    int*    swin = (int*)(Ksm + OO + 2);

    const int b   = blockIdx.y;
    const int ch  = blockIdx.x;
    const int hw0 = ch * HWB;
    const int tid = threadIdx.x;
    const int o   = tid >> 5;
    const int c   = tid & 31;

    // ---- prologue ---------------------------------------------------------
    {
        const float4* src4 = (const float4*)(pose + (size_t)(b * HW + hw0) * CC * 16);
        for (int idx = tid; idx < HWB * CC * 4; idx += TPB) {
            const int t_l = idx >> 7;
            const int rem = idx & 127;
            sp4[(t_l * 32 + (rem >> 2)) * 5 + (rem & 3)] = src4[idx];
        }
        const float* asrc = act + (size_t)(b * HW + hw0) * CC;
        for (int idx = tid; idx < HWB * CC; idx += TPB)
            sa[idx] = asrc[idx];
        if (tid < OO * 8) {
            const int po = tid >> 3, pk = tid & 7;
            const float* pp = g_params + (size_t)(b * OO + po) * 33;
            prm[po * 8 + pk] = make_float4(pp[1 + 2*pk], pp[2 + 2*pk],
                                           pp[17 + 2*pk], pp[18 + 2*pk]);
        }
        if (tid < OO) Ksm[tid] = g_params[(size_t)(b * OO + tid) * 33];
    }

    // per-thread w[c][o], rows packed as column pairs (R4 layout)
    u64 wv[4][2];
    {
        const float4* wp = (const float4*)(w + (size_t)(c * OO + o) * 16);
        #pragma unroll
        for (int j = 0; j < 4; j++) {
            const float4 r = wp[j];
            wv[j][0] = pack2(r.x, r.y);
            wv[j][1] = pack2(r.z, r.w);
        }
    }
    __syncthreads();
    const float K = Ksm[o];

    // ---- P1: logits for all t --------------------------------------------
    for (int t = 0; t < HWB; t++) {
        const int hw   = hw0 + t;
        const int h    = hw / WWD;
        const int wpos = hw - h * WWD;

        const float4* row = sp4 + (t * 32 + c) * 5;
        u64 v[8];
        #pragma unroll
        for (int i = 0; i < 4; i++) {
            const float4 P = row[i];
            const u64 p0 = pdup(P.x), p1 = pdup(P.y), p2 = pdup(P.z), p3 = pdup(P.w);
            v[i*2+0] = fma2(p0, wv[0][0], fma2(p1, wv[1][0],
                       fma2(p2, wv[2][0], mul2(p3, wv[3][0]))));
            v[i*2+1] = fma2(p0, wv[0][1], fma2(p1, wv[1][1],
                       fma2(p2, wv[2][1], mul2(p3, wv[3][1]))));
        }
        v[1] = add2(v[1], pack2(0.f, (wpos + 0.5f) * (1.0f / WWD)));
        v[3] = add2(v[3], pack2(0.f, (h    + 0.5f) * (1.0f / HH)));

        u64 e1 = 0ull, e2 = 0ull;
        #pragma unroll
        for (int k = 0; k < 8; k++) {
            const longlong2 q = *(const longlong2*)&prm[o * 8 + k];
            e1 = fma2(mul2(v[k], v[k]), (u64)q.x, e1);
            e2 = fma2(v[k], (u64)q.y, e2);
        }
        float e1l, e1h, e2l, e2h;
        unpack2(e1, e1l, e1h);
        unpack2(e2, e2l, e2h);
        ss[(t * 32 + c) * 11 + o] = fmaf(-0.5f, e1l + e1h, K + e2l + e2h);
    }
    __syncthreads();

    // ---- P2a: exps --------------------------------------------------------
    for (int t = 0; t < HWB; t++) {
        const float* r = ss + (t * 32 + c) * 11;
        float mx = r[0];
        #pragma unroll
        for (int oo = 1; oo < OO; oo++) mx = fmaxf(mx, r[oo]);
        se[(t * 32 + c) * 11 + o] = __expf(r[o] - mx);
    }
    __syncthreads();

    // ---- P2b: accumulate --------------------------------------------------
    float S0 = 0.f;
    u64 S1[8], S2[8];
    #pragma unroll
    for (int k = 0; k < 8; k++) { S1[k] = 0ull; S2[k] = 0ull; }

    for (int t = 0; t < HWB; t++) {
        const int hw   = hw0 + t;
        const int h    = hw / WWD;
        const int wpos = hw - h * WWD;

        const float* r = se + (t * 32 + c) * 11;
        float den = r[0];
        #pragma unroll
        for (int oo = 1; oo < OO; oo++) den += r[oo];
        const float ap = sa[t * 32 + c] * __fdividef(r[o], den);

        const float4* row = sp4 + (t * 32 + c) * 5;
        u64 v[8];
        #pragma unroll
        for (int i = 0; i < 4; i++) {
            const float4 P = row[i];
            const u64 p0 = pdup(P.x), p1 = pdup(P.y), p2 = pdup(P.z), p3 = pdup(P.w);
            v[i*2+0] = fma2(p0, wv[0][0], fma2(p1, wv[1][0],
                       fma2(p2, wv[2][0], mul2(p3, wv[3][0]))));
            v[i*2+1] = fma2(p0, wv[0][1], fma2(p1, wv[1][1],
                       fma2(p2, wv[2][1], mul2(p3, wv[3][1]))));
        }
        v[1] = add2(v[1], pack2(0.f, (wpos + 0.5f) * (1.0f / WWD)));
        v[3] = add2(v[3], pack2(0.f, (h    + 0.5f) * (1.0f / HH)));

        S0 += ap;
        const u64 ap2 = pdup(ap);
        #pragma unroll
        for (int k = 0; k < 8; k++) {
            const u64 t1 = mul2(ap2, v[k]);
            S1[k] = add2(S1[k], t1);
            S2[k] = fma2(t1, v[k], S2[k]);
        }
    }

    // ---- reduce over 32 c's ----------------------------------------------
    #pragma unroll
    for (int off = 16; off > 0; off >>= 1) {
        S0 += __shfl_xor_sync(0xFFFFFFFFu, S0, off);
        #pragma unroll
        for (int k = 0; k < 8; k++) {
            u64 a1 = __shfl_xor_sync(0xFFFFFFFFu, S1[k], off);
            u64 a2 = __shfl_xor_sync(0xFFFFFFFFu, S2[k], off);
            S1[k] = add2(S1[k], a1);
            S2[k] = add2(S2[k], a2);
        }
    }
    if (c == 0) {
        float* dst = g_partials + (size_t)((b * NCH + ch) * OO + o) * 33;
        dst[0] = S0;
        #pragma unroll
        for (int k = 0; k < 8; k++) {
            float lo, hi;
            unpack2(S1[k], lo, hi);
            dst[1 + 2*k] = lo;  dst[2 + 2*k] = hi;
            unpack2(S2[k], lo, hi);
            dst[17 + 2*k] = lo; dst[18 + 2*k] = hi;
        }
    }

    // ---- winner block per batch does the reduce --------------------------
    __syncthreads();
    if (tid == 0) {
        __threadfence();
        int prev = atomicAdd(&g_count[b], 1);
        *swin = (prev == NCH - 1);
    }
    __syncthreads();
    if (!*swin) return;
    __threadfence();

    if (tid < OO * 16) {
        const int ro = tid >> 4;
        const int rd = tid & 15;

        float R0 = 0.f, R1 = 0.f, R2 = 0.f;
        #pragma unroll 2
        for (int g = 0; g < NCH; g++) {
            const float* p = g_partials + (size_t)((b * NCH + g) * OO + ro) * 33;
            R0 += p[0];
            R1 += p[1 + rd];
            R2 += p[17 + rd];
        }

        const float rs     = R0 + EPSF;
        const float inv_rs = 1.0f / rs;
        const float mu     = R1 * inv_rs;
        const float var    = fmaxf(R2 * inv_rs - mu * mu, 0.0f) + EPSF;
        const float lv     = __logf(var);
        const float ivar   = 1.0f / var;
        const float muinv  = mu * ivar;
        const float mive   = mu * muinv;

        float sumlv = lv, summive = mive;
        #pragma unroll
        for (int off = 1; off < 16; off <<= 1) {
            sumlv   += __shfl_xor_sync(0xFFFFFFFFu, sumlv,   off);
            summive += __shfl_xor_sync(0xFFFFFFFFu, summive, off);
        }

        const float cost = rs * (16.0f * beta_u[ro] + 0.5f * sumlv);
        const float x    = inv_temp * (beta_a[ro] - cost);
        const float actv = 1.0f / (1.0f + __expf(-x));

        if (FINAL) {
            out[(size_t)(b * OO + ro) * 16 + rd] = mu;
            if (rd == 0) out[BB * OO * 16 + b * OO + ro] = actv;
        } else {
            float* pp = g_params + (size_t)(b * OO + ro) * 33;
            pp[1 + rd]  = ivar;
            pp[17 + rd] = muinv;
            if (rd == 0)
                pp[0] = __logf(actv + EPSF)
                      - 0.5f * (16.0f * LOG2PI + sumlv)
                      - 0.5f * summive;
        }
    }
    if (tid == 0) g_count[b] = 0;
}

// ---------------------------------------------------------------------------
extern "C" void kernel_launch(void* const* d_in, const int* in_sizes, int n_in,
                              void* d_out, int out_size)
{
    const float* pose = (const float*)d_in[0];
    const float* act  = (const float*)d_in[1];
    const float* w    = (const float*)d_in[2];
    const float* ba   = (const float*)d_in[3];
    const float* bu   = (const float*)d_in[4];
    float* out = (float*)d_out;

    static int smem_set = 0;
    if (!smem_set) {   // driver state only; capture-safe
        cudaFuncSetAttribute(caps_em<0>, cudaFuncAttributeMaxDynamicSharedMemorySize, SMEM_EM);
        cudaFuncSetAttribute(caps_em<1>, cudaFuncAttributeMaxDynamicSharedMemorySize, SMEM_EM);
        smem_set = 1;
    }

    dim3 g0(MCH, BB);
    dim3 ga(NCH, BB);

    caps_mom<<<g0, 256>>>(pose, act, w, ba, bu);                          // it=0 (moments)
    caps_em<0><<<ga, TPB, SMEM_EM>>>(pose, act, w, ba, bu, 2.0f, out);    // it=1
    caps_em<1><<<ga, TPB, SMEM_EM>>>(pose, act, w, ba, bu, 3.0f, out);    // it=2 -> out
}

// round 14
// speedup vs baseline: 1.4105x; 1.4105x over previous
#include <cuda_runtime.h>

#define BB 64
#define HH 14
#define WWD 14
#define HW 196
#define CC 32
#define OO 10
#define NCH 7               // em hw-chunks per batch
#define HWB (HW/NCH)        // 28
#define TPB 320             // 10 warps: warp = o, lane = c
#define ACH 7               // pass0 chunks per batch
#define AHW (HW/ACH)        // 28
#define ATPB 160            // pass0: 5 warps
#define EPSF 1e-9f
#define LOG2PI 1.8378770664093453f

typedef unsigned long long u64;

// ---- f32x2 packed math (Blackwell) ---------------------------------------
__device__ __forceinline__ u64 pack2(float lo, float hi) {
    u64 r; asm("mov.b64 %0, {%1,%2};" : "=l"(r) : "f"(lo), "f"(hi)); return r;
}
__device__ __forceinline__ u64 pdup(float x) { return pack2(x, x); }
__device__ __forceinline__ void unpack2(u64 v, float& lo, float& hi) {
    asm("mov.b64 {%0,%1}, %2;" : "=f"(lo), "=f"(hi) : "l"(v));
}
__device__ __forceinline__ u64 fma2(u64 a, u64 b, u64 c) {
    u64 d; asm("fma.rn.f32x2 %0,%1,%2,%3;" : "=l"(d) : "l"(a), "l"(b), "l"(c)); return d;
}
__device__ __forceinline__ u64 mul2(u64 a, u64 b) {
    u64 d; asm("mul.rn.f32x2 %0,%1,%2;" : "=l"(d) : "l"(a), "l"(b)); return d;
}
__device__ __forceinline__ u64 add2(u64 a, u64 b) {
    u64 d; asm("add.rn.f32x2 %0,%1,%2;" : "=l"(d) : "l"(a), "l"(b)); return d;
}

// Scratch (fully rewritten every pass -> deterministic, graph-safe)
__device__ float g_partials[BB*NCH*OO*33];   // [b][chunk][o][S0,S1[16],S2[16]]
__device__ float g_params[BB*OO*33];         // [b][o][K, ivar[16], muinv[16]]
__device__ float g_mom[BB*ACH*CC*70];        // pass0 per-chunk combined moments
__device__ int   g_count[BB];                // em counters (winner resets)
__device__ int   g_cnt0[BB];                 // pass0 counters (winner resets)

// ===========================================================================
// PASS 0 via moments (rr = 1/O). grid=(ACH,BB), block=160 (5 warps).
// lane = c (coalesced LDG), warp = hw-strider. A[69] in registers, per-warp
// stage in smem, block combine -> g_mom, fused winner assembles params.
// Moment layout per c (69): [0]=sum a; [1..16]=sum a*p_j;
// [17+10i+idx(j<=k)]=sum a*p_{4i+j}p_{4i+k}; [57]aw [58]ah [59]aw2 [60]ah2;
// [61..64]=a*ow*p_{0..3}; [65..68]=a*oh*p_{4..7}.
// ===========================================================================
__global__ void __launch_bounds__(ATPB)
caps_mom(const float* __restrict__ pose,
         const float* __restrict__ act,
         const float* __restrict__ w,
         const float* __restrict__ beta_a,
         const float* __restrict__ beta_u)
{
    __shared__ float stage[5][CC][70];   // 44.8 KB
    __shared__ int   s_win;

    const int ch  = blockIdx.x;
    const int b   = blockIdx.y;
    const int tid = threadIdx.x;
    const int wp  = tid >> 5;     // 0..4
    const int c   = tid & 31;

    float A[69];
    #pragma unroll
    for (int m = 0; m < 69; m++) A[m] = 0.f;

    for (int hwl = wp; hwl < AHW; hwl += 5) {
        const int hw = ch * AHW + hwl;
        const float4* pp = (const float4*)(pose + ((size_t)(b * HW + hw) * CC + c) * 16);
        float p[16];
        #pragma unroll
        for (int q = 0; q < 4; q++) {
            const float4 t4 = pp[q];
            p[q*4+0] = t4.x; p[q*4+1] = t4.y; p[q*4+2] = t4.z; p[q*4+3] = t4.w;
        }
        const float a = act[(size_t)(b * HW + hw) * CC + c];
        const int h    = hw / WWD;
        const int wpos = hw - h * WWD;
        const float ow = (wpos + 0.5f) * (1.0f / WWD);
        const float oh = (h    + 0.5f) * (1.0f / HH);

        float ap[16];
        #pragma unroll
        for (int j = 0; j < 16; j++) ap[j] = a * p[j];

        A[0] += a;
        #pragma unroll
        for (int j = 0; j < 16; j++) A[1 + j] += ap[j];
        #pragma unroll
        for (int i = 0; i < 4; i++) {
            const int mb = 17 + i * 10;
            const int pb = i * 4;
            int idx = 0;
            #pragma unroll
            for (int j = 0; j < 4; j++)
                #pragma unroll
                for (int k = j; k < 4; k++)
                    A[mb + (idx++)] += ap[pb + j] * p[pb + k];
        }
        const float aw = a * ow, ah = a * oh;
        A[57] += aw; A[58] += ah;
        A[59] += aw * ow; A[60] += ah * oh;
        #pragma unroll
        for (int j = 0; j < 4; j++) {
            A[61 + j] += aw * p[j];
            A[65 + j] += ah * p[4 + j];
        }
    }

    // stage per-warp partials, combine over 5 warps -> g_mom
    #pragma unroll
    for (int m = 0; m < 69; m++) stage[wp][c][m] = A[m];
    __syncthreads();
    for (int idx = tid; idx < CC * 69; idx += ATPB) {
        const int cc = idx / 69;
        const int m  = idx - cc * 69;
        float s = stage[0][cc][m];
        #pragma unroll
        for (int ww = 1; ww < 5; ww++) s += stage[ww][cc][m];
        g_mom[(size_t)((b * ACH + ch) * CC + cc) * 70 + m] = s;
    }

    // ---- winner block per batch assembles params --------------------------
    __syncthreads();
    if (tid == 0) {
        __threadfence();
        int prev = atomicAdd(&g_cnt0[b], 1);
        s_win = (prev == ACH - 1);
    }
    __syncthreads();
    if (!s_win) return;
    __threadfence();

    float (*mom)[70] = (float (*)[70])(&stage[0][0][0]);   // alias stage
    for (int idx = tid; idx < CC * 69; idx += ATPB) {
        const int cc = idx / 69;
        const int m  = idx - cc * 69;
        float s = 0.f;
        #pragma unroll
        for (int g = 0; g < ACH; g++)
            s += g_mom[(size_t)((b * ACH + g) * CC + cc) * 70 + m];
        mom[cc][m] = s;
    }
    __syncthreads();

    {   // tid < 160 == all threads: one (o,d) each
        const int o   = tid >> 4;
        const int d   = tid & 15;
        const int i   = d >> 2;
        const int col = d & 3;

        float R0 = 0.f, S1 = 0.f, S2 = 0.f;
        for (int cc = 0; cc < CC; cc++) {
            const float* mc2 = mom[cc];
            const float* wc = w + ((size_t)(cc * OO + o) * 16) + col;
            const float w0 = wc[0], w1 = wc[4], w2 = wc[8], w3 = wc[12];
            R0 += mc2[0];
            const float* m1 = mc2 + 1 + i * 4;
            S1 += m1[0]*w0 + m1[1]*w1 + m1[2]*w2 + m1[3]*w3;
            const float* M = mc2 + 17 + i * 10;
            S2 += w0*w0*M[0] + w1*w1*M[4] + w2*w2*M[7] + w3*w3*M[9]
                + 2.f*(w0*w1*M[1] + w0*w2*M[2] + w0*w3*M[3]
                     + w1*w2*M[5] + w1*w3*M[6] + w2*w3*M[8]);
            if (d == 3) {
                S1 += mc2[57];
                S2 += mc2[59] + 2.f*(mc2[61]*w0 + mc2[62]*w1 + mc2[63]*w2 + mc2[64]*w3);
            }
            if (d == 7) {
                S1 += mc2[58];
                S2 += mc2[60] + 2.f*(mc2[65]*w0 + mc2[66]*w1 + mc2[67]*w2 + mc2[68]*w3);
            }
        }
        const float rs     = 0.1f * R0 + EPSF;
        const float inv_rs = 1.0f / rs;
        const float mu     = 0.1f * S1 * inv_rs;
        const float var    = fmaxf(0.1f * S2 * inv_rs - mu * mu, 0.0f) + EPSF;
        const float lv     = __logf(var);
        const float ivar   = 1.0f / var;
        const float muinv  = mu * ivar;
        const float mive   = mu * muinv;

        float sumlv = lv, summive = mive;
        #pragma unroll
        for (int off = 1; off < 16; off <<= 1) {
            sumlv   += __shfl_xor_sync(0xFFFFFFFFu, sumlv,   off);
            summive += __shfl_xor_sync(0xFFFFFFFFu, summive, off);
        }

        const float cost = rs * (16.0f * beta_u[o] + 0.5f * sumlv);
        const float actv = 1.0f / (1.0f + __expf(-(beta_a[o] - cost))); // inv_temp=1

        float* pp = g_params + (size_t)(b * OO + o) * 33;
        pp[1 + d]  = ivar;
        pp[17 + d] = muinv;
        if (d == 0)
            pp[0] = __logf(actv + EPSF)
                  - 0.5f * (16.0f * LOG2PI + sumlv)
                  - 0.5f * summive;
    }
    if (tid == 0) g_cnt0[b] = 0;
}

// ===========================================================================
// EM passes 1/2: per-t softmax (2 barriers/t), HWB=28, grid (7,BB).
// ss/se packed at stride 12 -> max/den via float4+float2 (3 loads vs 10).
// Dynamic smem: sp4 71680 | prm 1280 | ss 1536 | se 1536 | sa 3584 | Ksm/swin.
// ===========================================================================
#define SMEM_EM (71680 + 1280 + 1536 + 1536 + 3584 + 64)

template<int FINAL>
__global__ void __launch_bounds__(TPB, 2)
caps_em(const float* __restrict__ pose,
        const float* __restrict__ act,
        const float* __restrict__ w,
        const float* __restrict__ beta_a,
        const float* __restrict__ beta_u,
        float inv_temp,
        float* __restrict__ out)
{
    extern __shared__ char smraw[];
    float4* sp4 = (float4*)smraw;                        // [28][32][5]
    float4* prm = (float4*)(smraw + 71680);              // [OO*8]
    float*  ss  = (float*)(smraw + 71680 + 1280);        // [32*12]
    float*  se  = ss + 32 * 12;                          // [32*12]
    float*  sa  = se + 32 * 12;                          // [28*32]
    float*  Ksm = sa + HWB * 32;                         // [OO]
    int*    swin = (int*)(Ksm + OO + 2);

    const int b   = blockIdx.y;
    const int ch  = blockIdx.x;
    const int hw0 = ch * HWB;
    const int tid = threadIdx.x;
    const int o   = tid >> 5;
    const int c   = tid & 31;

    // ---- prologue ---------------------------------------------------------
    {
        const float4* src4 = (const float4*)(pose + (size_t)(b * HW + hw0) * CC * 16);
        for (int idx = tid; idx < HWB * CC * 4; idx += TPB) {
            const int t_l = idx >> 7;
            const int rem = idx & 127;
            sp4[(t_l * 32 + (rem >> 2)) * 5 + (rem & 3)] = src4[idx];
        }
        const float* asrc = act + (size_t)(b * HW + hw0) * CC;
        for (int idx = tid; idx < HWB * CC; idx += TPB)
            sa[idx] = asrc[idx];
        if (tid < OO * 8) {
            const int po = tid >> 3, pk = tid & 7;
            const float* pp = g_params + (size_t)(b * OO + po) * 33;
            prm[po * 8 + pk] = make_float4(pp[1 + 2*pk], pp[2 + 2*pk],
                                           pp[17 + 2*pk], pp[18 + 2*pk]);
        }
        if (tid < OO) Ksm[tid] = g_params[(size_t)(b * OO + tid) * 33];
    }

    // per-thread w[c][o], rows packed as column pairs
    u64 wv[4][2];
    {
        const float4* wp = (const float4*)(w + (size_t)(c * OO + o) * 16);
        #pragma unroll
        for (int j = 0; j < 4; j++) {
            const float4 r = wp[j];
            wv[j][0] = pack2(r.x, r.y);
            wv[j][1] = pack2(r.z, r.w);
        }
    }

    float S0 = 0.f;
    u64 S1[8], S2[8];
    #pragma unroll
    for (int k = 0; k < 8; k++) { S1[k] = 0ull; S2[k] = 0ull; }

    __syncthreads();
    const float K = Ksm[o];

    for (int t = 0; t < HWB; t++) {
        const int hw   = hw0 + t;
        const int h    = hw / WWD;
        const int wpos = hw - h * WWD;

        // votes (held through softmax)
        const float4* row = sp4 + (t * 32 + c) * 5;
        u64 v[8];
        #pragma unroll
        for (int i = 0; i < 4; i++) {
            const float4 P = row[i];
            const u64 p0 = pdup(P.x), p1 = pdup(P.y), p2 = pdup(P.z), p3 = pdup(P.w);
            v[i*2+0] = fma2(p0, wv[0][0], fma2(p1, wv[1][0],
                       fma2(p2, wv[2][0], mul2(p3, wv[3][0]))));
            v[i*2+1] = fma2(p0, wv[0][1], fma2(p1, wv[1][1],
                       fma2(p2, wv[2][1], mul2(p3, wv[3][1]))));
        }
        v[1] = add2(v[1], pack2(0.f, (wpos + 0.5f) * (1.0f / WWD)));
        v[3] = add2(v[3], pack2(0.f, (h    + 0.5f) * (1.0f / HH)));

        // logit
        u64 e1 = 0ull, e2 = 0ull;
        #pragma unroll
        for (int k = 0; k < 8; k++) {
            const longlong2 q = *(const longlong2*)&prm[o * 8 + k];   // uniform
            e1 = fma2(mul2(v[k], v[k]), (u64)q.x, e1);
            e2 = fma2(v[k], (u64)q.y, e2);
        }
        float e1l, e1h, e2l, e2h;
        unpack2(e1, e1l, e1h);
        unpack2(e2, e2l, e2h);
        const float s = fmaf(-0.5f, e1l + e1h, K + e2l + e2h);

        ss[c * 12 + o] = s;
        __syncthreads();
        const float4 q0 = *(const float4*)(ss + c * 12);
        const float4 q1 = *(const float4*)(ss + c * 12 + 4);
        const float2 q2 = *(const float2*)(ss + c * 12 + 8);
        const float mx = fmaxf(fmaxf(fmaxf(fmaxf(q0.x, q0.y), fmaxf(q0.z, q0.w)),
                               fmaxf(fmaxf(q1.x, q1.y), fmaxf(q1.z, q1.w))),
                               fmaxf(q2.x, q2.y));
        const float e = __expf(s - mx);
        se[c * 12 + o] = e;
        __syncthreads();
        const float4 r0 = *(const float4*)(se + c * 12);
        const float4 r1 = *(const float4*)(se + c * 12 + 4);
        const float2 r2 = *(const float2*)(se + c * 12 + 8);
        const float den = (((r0.x + r0.y) + (r0.z + r0.w))
                         + ((r1.x + r1.y) + (r1.z + r1.w))) + (r2.x + r2.y);
        const float ap = sa[t * 32 + c] * __fdividef(e, den);

        S0 += ap;
        const u64 ap2 = pdup(ap);
        #pragma unroll
        for (int k = 0; k < 8; k++) {
            const u64 t1 = mul2(ap2, v[k]);
            S1[k] = add2(S1[k], t1);
            S2[k] = fma2(t1, v[k], S2[k]);
        }
    }

    // ---- reduce over 32 c's ----------------------------------------------
    #pragma unroll
    for (int off = 16; off > 0; off >>= 1) {
        S0 += __shfl_xor_sync(0xFFFFFFFFu, S0, off);
        #pragma unroll
        for (int k = 0; k < 8; k++) {
            u64 a1 = __shfl_xor_sync(0xFFFFFFFFu, S1[k], off);
            u64 a2 = __shfl_xor_sync(0xFFFFFFFFu, S2[k], off);
            S1[k] = add2(S1[k], a1);
            S2[k] = add2(S2[k], a2);
        }
    }
    if (c == 0) {
        float* dst = g_partials + (size_t)((b * NCH + ch) * OO + o) * 33;
        dst[0] = S0;
        #pragma unroll
        for (int k = 0; k < 8; k++) {
            float lo, hi;
            unpack2(S1[k], lo, hi);
            dst[1 + 2*k] = lo;  dst[2 + 2*k] = hi;
            unpack2(S2[k], lo, hi);
            dst[17 + 2*k] = lo; dst[18 + 2*k] = hi;
        }
    }

    // ---- winner block per batch does the reduce --------------------------
    __syncthreads();
    if (tid == 0) {
        __threadfence();
        int prev = atomicAdd(&g_count[b], 1);
        *swin = (prev == NCH - 1);
    }
    __syncthreads();
    if (!*swin) return;
    __threadfence();

    if (tid < OO * 16) {
        const int ro = tid >> 4;
        const int rd = tid & 15;

        float R0 = 0.f, R1 = 0.f, R2 = 0.f;
        #pragma unroll
        for (int g = 0; g < NCH; g++) {
            const float* p = g_partials + (size_t)((b * NCH + g) * OO + ro) * 33;
            R0 += p[0];
            R1 += p[1 + rd];
            R2 += p[17 + rd];
        }

        const float rs     = R0 + EPSF;
        const float inv_rs = 1.0f / rs;
        const float mu     = R1 * inv_rs;
        const float var    = fmaxf(R2 * inv_rs - mu * mu, 0.0f) + EPSF;
        const float lv     = __logf(var);
        const float ivar   = 1.0f / var;
        const float muinv  = mu * ivar;
        const float mive   = mu * muinv;

        float sumlv = lv, summive = mive;
        #pragma unroll
        for (int off = 1; off < 16; off <<= 1) {
            sumlv   += __shfl_xor_sync(0xFFFFFFFFu, sumlv,   off);
            summive += __shfl_xor_sync(0xFFFFFFFFu, summive, off);
        }

        const float cost = rs * (16.0f * beta_u[ro] + 0.5f * sumlv);
        const float x    = inv_temp * (beta_a[ro] - cost);
        const float actv = 1.0f / (1.0f + __expf(-x));

        if (FINAL) {
            out[(size_t)(b * OO + ro) * 16 + rd] = mu;
            if (rd == 0) out[BB * OO * 16 + b * OO + ro] = actv;
        } else {
            float* pp = g_params + (size_t)(b * OO + ro) * 33;
            pp[1 + rd]  = ivar;
            pp[17 + rd] = muinv;
            if (rd == 0)
                pp[0] = __logf(actv + EPSF)
                      - 0.5f * (16.0f * LOG2PI + sumlv)
                      - 0.5f * summive;
        }
    }
    if (tid == 0) g_count[b] = 0;
}

// ---------------------------------------------------------------------------
extern "C" void kernel_launch(void* const* d_in, const int* in_sizes, int n_in,
                              void* d_out, int out_size)
{
    const float* pose = (const float*)d_in[0];
    const float* act  = (const float*)d_in[1];
    const float* w    = (const float*)d_in[2];
    const float* ba   = (const float*)d_in[3];
    const float* bu   = (const float*)d_in[4];
    float* out = (float*)d_out;

    static int smem_set = 0;
    if (!smem_set) {   // driver state only; capture-safe
        cudaFuncSetAttribute(caps_em<0>, cudaFuncAttributeMaxDynamicSharedMemorySize, SMEM_EM);
        cudaFuncSetAttribute(caps_em<1>, cudaFuncAttributeMaxDynamicSharedMemorySize, SMEM_EM);
        smem_set = 1;
    }

    dim3 g0(ACH, BB);
    dim3 ga(NCH, BB);

    caps_mom<<<g0, ATPB>>>(pose, act, w, ba, bu);                         // it=0
    caps_em<0><<<ga, TPB, SMEM_EM>>>(pose, act, w, ba, bu, 2.0f, out);    // it=1
    caps_em<1><<<ga, TPB, SMEM_EM>>>(pose, act, w, ba, bu, 3.0f, out);    // it=2
}